// round 8
// baseline (speedup 1.0000x reference)
#include <cuda_runtime.h>
#include <math.h>
#include <stdint.h>

#define S_DIM  384
#define CZ     128
#define H_DIM  4
#define CH     32
#define NROWS  (S_DIM*S_DIM)   // 147456

// ---------------- scratch (device globals; allocation-free) ----------------
__device__ float g_q [(size_t)NROWS*CZ];   // q projection  (col = h*32+c)
__device__ float g_g [(size_t)NROWS*CZ];   // sigmoid gate  (col = h*32+c)
__device__ float g_k [(size_t)NROWS*CH];   // k projection  [i*384+kk][c]
__device__ float g_v [(size_t)NROWS*CH];   // v projection

// ---------------- helpers ----------------
__device__ __forceinline__ uint32_t f2tf32(float f) {
    uint32_t u; asm("cvt.rna.tf32.f32 %0, %1;" : "=r"(u) : "f"(f)); return u;
}
__device__ __forceinline__ void mma_tf32(float* d, const uint32_t* a, const uint32_t* b) {
    asm volatile(
        "mma.sync.aligned.m16n8k8.row.col.f32.tf32.tf32.f32 "
        "{%0,%1,%2,%3}, {%4,%5,%6,%7}, {%8,%9}, {%0,%1,%2,%3};\n"
        : "+f"(d[0]), "+f"(d[1]), "+f"(d[2]), "+f"(d[3])
        : "r"(a[0]), "r"(a[1]), "r"(a[2]), "r"(a[3]), "r"(b[0]), "r"(b[1]));
}
// load 4 fp32 from smem (A fragment layout) and split into hi/lo tf32
__device__ __forceinline__ void load_split(const float* smf, int i0, int i1, int i2, int i3,
                                           uint32_t* ah, uint32_t* al) {
    float a0 = smf[i0], a1 = smf[i1], a2 = smf[i2], a3 = smf[i3];
    ah[0] = f2tf32(a0); al[0] = f2tf32(a0 - __uint_as_float(ah[0]));
    ah[1] = f2tf32(a1); al[1] = f2tf32(a1 - __uint_as_float(ah[1]));
    ah[2] = f2tf32(a2); al[2] = f2tf32(a2 - __uint_as_float(ah[2]));
    ah[3] = f2tf32(a3); al[3] = f2tf32(a3 - __uint_as_float(ah[3]));
}
__device__ __forceinline__ void split4(float4 af, uint32_t* ah, uint32_t* al) {
    ah[0] = f2tf32(af.x); al[0] = f2tf32(af.x - __uint_as_float(ah[0]));
    ah[1] = f2tf32(af.y); al[1] = f2tf32(af.y - __uint_as_float(ah[1]));
    ah[2] = f2tf32(af.z); al[2] = f2tf32(af.z - __uint_as_float(ah[2]));
    ah[3] = f2tf32(af.w); al[3] = f2tf32(af.w - __uint_as_float(ah[3]));
}

// ---------------- kernel 1: LayerNorm + fused projections (tf32 HMMA) ----------------
// (unchanged from R7 — known good at ~240us; target next round)
#define PA_STR 132
#define PB_STR 68
#define PROJ_SMEM (64*PA_STR*4 + 160*PB_STR*4)   // 77312 B
__global__ void __launch_bounds__(512, 2) proj_mma(const float* __restrict__ z,
                                                   const float* __restrict__ lnw,
                                                   const float* __restrict__ lnb,
                                                   const float* __restrict__ Wq,
                                                   const float* __restrict__ Wk,
                                                   const float* __restrict__ Wv,
                                                   const float* __restrict__ Wg,
                                                   const float* __restrict__ bg)
{
    extern __shared__ float sm[];
    float* As = sm;
    uint32_t* Bsu = reinterpret_cast<uint32_t*>(sm + 64 * PA_STR);

    const int tid  = threadIdx.x;
    const int wid  = tid >> 5;
    const int lane = tid & 31;
    const int r = lane >> 2, c = lane & 3;
    const int wm = wid & 3, wn = wid >> 2;
    const int m0 = wm * 16, n0 = wn * 40;
    const int rowBase = blockIdx.x * 64;
    const int cg = blockIdx.y;

    {
        int row = tid >> 3;
        int sub = tid & 7;
        const float4* zr = reinterpret_cast<const float4*>(z + (size_t)(rowBase + row) * CZ) + sub * 4;
        float4 x0 = zr[0], x1 = zr[1], x2 = zr[2], x3 = zr[3];
        float s  = x0.x+x0.y+x0.z+x0.w + x1.x+x1.y+x1.z+x1.w
                 + x2.x+x2.y+x2.z+x2.w + x3.x+x3.y+x3.z+x3.w;
        float ss = x0.x*x0.x+x0.y*x0.y+x0.z*x0.z+x0.w*x0.w
                 + x1.x*x1.x+x1.y*x1.y+x1.z*x1.z+x1.w*x1.w
                 + x2.x*x2.x+x2.y*x2.y+x2.z*x2.z+x2.w*x2.w
                 + x3.x*x3.x+x3.y*x3.y+x3.z*x3.z+x3.w*x3.w;
        #pragma unroll
        for (int o = 1; o < 8; o <<= 1) {
            s  += __shfl_xor_sync(0xffffffffu, s,  o);
            ss += __shfl_xor_sync(0xffffffffu, ss, o);
        }
        float mean = s * (1.0f / CZ);
        float var  = ss * (1.0f / CZ) - mean * mean;
        float rstd = rsqrtf(var + 1e-5f);
        const float4* wv4 = reinterpret_cast<const float4*>(lnw) + sub * 4;
        const float4* bv4 = reinterpret_cast<const float4*>(lnb) + sub * 4;
        float xs[16] = {x0.x,x0.y,x0.z,x0.w, x1.x,x1.y,x1.z,x1.w,
                        x2.x,x2.y,x2.z,x2.w, x3.x,x3.y,x3.z,x3.w};
        #pragma unroll
        for (int q = 0; q < 4; q++) {
            float4 wv = wv4[q], bv = bv4[q];
            float wq[4] = {wv.x, wv.y, wv.z, wv.w};
            float bq[4] = {bv.x, bv.y, bv.z, bv.w};
            #pragma unroll
            for (int e = 0; e < 4; e++) {
                As[row * PA_STR + sub * 16 + q * 4 + e] =
                    (xs[q * 4 + e] - mean) * rstd * wq[e] + bq[e];
            }
        }
    }

    float acc[5][4] = {};
    #pragma unroll
    for (int kh = 0; kh < 2; kh++) {
        if (kh) __syncthreads();
        #pragma unroll
        for (int t = 0; t < 5; t++) {
            int idx = tid + t * 512;
            int rr = idx >> 4, c4 = idx & 15;
            int gc = cg * 160 + rr;
            const float* wrow;
            if (gc < 128)      wrow = Wq + (size_t)gc * CZ;
            else if (gc < 160) wrow = Wk + (size_t)(gc - 128) * CZ;
            else if (gc < 192) wrow = Wv + (size_t)(gc - 160) * CZ;
            else               wrow = Wg + (size_t)(gc - 192) * CZ;
            float4 v = reinterpret_cast<const float4*>(wrow)[kh * 16 + c4];
            Bsu[rr * PB_STR + c4 * 4 + 0] = f2tf32(v.x);
            Bsu[rr * PB_STR + c4 * 4 + 1] = f2tf32(v.y);
            Bsu[rr * PB_STR + c4 * 4 + 2] = f2tf32(v.z);
            Bsu[rr * PB_STR + c4 * 4 + 3] = f2tf32(v.w);
        }
        __syncthreads();
        #pragma unroll
        for (int ks = 0; ks < 8; ks++) {
            int k0 = ks * 8;
            int ka = kh * 64 + k0;
            uint32_t ah[4], al[4];
            load_split(As,
                (m0 + r) * PA_STR + ka + c,     (m0 + r + 8) * PA_STR + ka + c,
                (m0 + r) * PA_STR + ka + c + 4, (m0 + r + 8) * PA_STR + ka + c + 4,
                ah, al);
            #pragma unroll
            for (int nt = 0; nt < 5; nt++) {
                uint32_t b[2];
                b[0] = Bsu[(n0 + nt * 8 + r) * PB_STR + k0 + c];
                b[1] = Bsu[(n0 + nt * 8 + r) * PB_STR + k0 + c + 4];
                mma_tf32(acc[nt], ah, b);
                mma_tf32(acc[nt], al, b);
            }
        }
    }

    #pragma unroll
    for (int nt = 0; nt < 5; nt++) {
        int gc = cg * 160 + n0 + nt * 8 + c * 2;
        #pragma unroll
        for (int half = 0; half < 2; half++) {
            size_t row = (size_t)rowBase + m0 + r + half * 8;
            float2 v = make_float2(acc[nt][half * 2], acc[nt][half * 2 + 1]);
            if (gc < 128)
                *reinterpret_cast<float2*>(&g_q[row * CZ + gc]) = v;
            else if (gc < 160)
                *reinterpret_cast<float2*>(&g_k[row * CH + (gc - 128)]) = v;
            else if (gc < 192)
                *reinterpret_cast<float2*>(&g_v[row * CH + (gc - 160)]) = v;
            else {
                int cc = gc - 192;
                v.x = 1.0f / (1.0f + __expf(-(v.x + bg[cc])));
                v.y = 1.0f / (1.0f + __expf(-(v.y + bg[cc + 1])));
                *reinterpret_cast<float2*>(&g_g[row * CZ + cc]) = v;
            }
        }
    }
}

// ---------------- kernel 2: attention + fused out-proj, FRAGMENT-PACKED smem ----------------
// All smem operands live in MMA-fragment order [block][lane][4] so every fragment
// group is ONE conflict-free LDS.128 per thread.
//   Qf[wm][h][kc][lane][4] : slots {row r col c, row r+8 col c, r c+4, r+8 c+4}  (tf32)
//   Kf[nb][kc2][lane][4]   : slots {kc=2kc2 b0,b1, kc=2kc2+1 b0,b1}              (tf32)
//   Vf[kb][nt2][lane][4]   : slots {nt even b0,b1, nt odd b0,b1}                 (tf32)
//   Of — aliases Qf slots per head (fp32, gated o), consumed by out-proj A loads
//   Wof[nb][kc2][lane][4]  : staged over dead Kf/Vf after the h loop
#define RED_OFF 0                        // 256 floats [wn][64]
#define QF_OFF  256                      // 4*4*4*128 = 8192
#define KF_OFF  (QF_OFF + 8192)          // 48*256 = 12288
#define VF_OFF  (KF_OFF + 12288)         // 48*256 = 12288
#define PT_OFF  (VF_OFF + 12288)         // 4*64*36 = 9216
#define PT_STR  36
#define ATTN_SMEM_F (PT_OFF + 4*64*PT_STR)   // 42240 floats
#define ATTN_SMEM_B (ATTN_SMEM_F * 4)        // 168960 B

__global__ void __launch_bounds__(512, 1) attn_mma_kernel(const float* __restrict__ Wo,
                                                          const float* __restrict__ bo,
                                                          float* __restrict__ out)
{
    extern __shared__ float smf[];
    uint32_t* smu = reinterpret_cast<uint32_t*>(smf);
    const int tid  = threadIdx.x;
    const int wid  = tid >> 5;
    const int lane = tid & 31;
    const int wm = wid & 3;
    const int wn = wid >> 2;
    const int r  = lane >> 2;
    const int c  = lane & 3;
    const int m0 = wm * 16;
    const int i  = blockIdx.x;
    const int jt = blockIdx.y;

    const float scale = 0.17677669529663689f;
    const size_t qrow0 = (size_t)i * S_DIM + jt * 64;
    const size_t kr0   = (size_t)i * S_DIM;

    // ---- stage Q into Qf (scaled tf32, fragment order) ----
    #pragma unroll
    for (int t = 0; t < 4; t++) {
        int idx = tid + t * 512;
        int rr = idx >> 5, c4 = idx & 31;
        float4 v = *reinterpret_cast<const float4*>(&g_q[(qrow0 + rr) * CZ + c4 * 4]);
        int h = c4 >> 3, kc = (c4 & 7) >> 1, chalf = c4 & 1;
        int wmq = rr >> 4, rh = (rr >> 3) & 1, rq = rr & 7;
        uint32_t* dst = &smu[QF_OFF + wmq*2048 + h*512 + kc*128 + rq*16 + chalf*2 + rh];
        dst[0]  = f2tf32(v.x * scale);
        dst[4]  = f2tf32(v.y * scale);
        dst[8]  = f2tf32(v.z * scale);
        dst[12] = f2tf32(v.w * scale);
    }
    // ---- stage K into Kf, V into Vf (tf32, fragment order) ----
    #pragma unroll
    for (int t = 0; t < 6; t++) {
        int idx = tid + t * 512;
        int rr = idx >> 3, c4 = idx & 7;      // rr = key index, ch = c4*4..+3
        float4 k4 = *reinterpret_cast<const float4*>(&g_k[(kr0 + rr) * CH + c4 * 4]);
        {
            int nb = rr >> 3, rq = rr & 7;
            int kc2 = c4 >> 2, kcl = (c4 >> 1) & 1, b = c4 & 1;
            uint32_t* kd = &smu[KF_OFF + nb*256 + kc2*128 + rq*16 + kcl*2 + b];
            kd[0] = f2tf32(k4.x); kd[4] = f2tf32(k4.y);
            kd[8] = f2tf32(k4.z); kd[12] = f2tf32(k4.w);
        }
        float4 v4 = *reinterpret_cast<const float4*>(&g_v[(kr0 + rr) * CH + c4 * 4]);
        {
            int kb = rr >> 3, cc = rr & 3, sx = (rr >> 2) & 1;
            int nt2 = c4 >> 2, rh = (c4 >> 1) & 1, rvb = (c4 & 1) * 4;
            uint32_t* vd = &smu[VF_OFF + kb*256 + nt2*128 + rvb*16 + cc*4 + rh*2 + sx];
            vd[0]  = f2tf32(v4.x); vd[16] = f2tf32(v4.y);
            vd[32] = f2tf32(v4.z); vd[48] = f2tf32(v4.w);
        }
    }
    __syncthreads();

    const int srcA = (lane & ~3) | (c >> 1);
    const int srcB = srcA + 2;
    const bool odd = (c & 1) != 0;

    for (int h = 0; h < H_DIM; h++) {
        // ---- A fragments: 4 x LDS.128 ----
        uint32_t afrag[4][4];
        #pragma unroll
        for (int kc = 0; kc < 4; kc++) {
            uint4 q = *reinterpret_cast<const uint4*>(
                &smu[QF_OFF + wm*2048 + h*512 + kc*128 + lane*4]);
            afrag[kc][0] = q.x; afrag[kc][1] = q.y;
            afrag[kc][2] = q.z; afrag[kc][3] = q.w;
        }
        // ---- GEMM1: 12 nb x (2 LDS.128 + 4 MMA) ----
        float acc1[6][2][4] = {};
        #pragma unroll
        for (int kt = 0; kt < 6; kt++) {
            #pragma unroll
            for (int j = 0; j < 2; j++) {
                int nb = kt * 8 + wn * 2 + j;
                uint4 f0 = *reinterpret_cast<const uint4*>(&smu[KF_OFF + nb*256 + lane*4]);
                uint4 f1 = *reinterpret_cast<const uint4*>(&smu[KF_OFF + nb*256 + 128 + lane*4]);
                uint32_t b0[2] = {f0.x, f0.y}, b1[2] = {f0.z, f0.w};
                uint32_t b2[2] = {f1.x, f1.y}, b3[2] = {f1.z, f1.w};
                mma_tf32(acc1[kt][j], afrag[0], b0);
                mma_tf32(acc1[kt][j], afrag[1], b1);
                mma_tf32(acc1[kt][j], afrag[2], b2);
                mma_tf32(acc1[kt][j], afrag[3], b3);
            }
        }
        // ---- exp in regs + row sums ----
        float rs0 = 0.0f, rs1 = 0.0f;
        #pragma unroll
        for (int kt = 0; kt < 6; kt++) {
            #pragma unroll
            for (int j = 0; j < 2; j++) {
                acc1[kt][j][0] = __expf(acc1[kt][j][0]);
                acc1[kt][j][1] = __expf(acc1[kt][j][1]);
                acc1[kt][j][2] = __expf(acc1[kt][j][2]);
                acc1[kt][j][3] = __expf(acc1[kt][j][3]);
                rs0 += acc1[kt][j][0] + acc1[kt][j][1];
                rs1 += acc1[kt][j][2] + acc1[kt][j][3];
            }
        }
        rs0 += __shfl_xor_sync(0xffffffffu, rs0, 1);
        rs0 += __shfl_xor_sync(0xffffffffu, rs0, 2);
        rs1 += __shfl_xor_sync(0xffffffffu, rs1, 1);
        rs1 += __shfl_xor_sync(0xffffffffu, rs1, 2);
        if (c == 0) {
            smf[RED_OFF + wn * 64 + m0 + r] = rs0;
            smf[RED_OFF + wn * 64 + m0 + 8 + r] = rs1;
        }
        // ---- GEMM2 split-K, register P via quad shuffles; V: 2 LDS.128 per kb ----
        float acc2[4][4] = {};
        #pragma unroll
        for (int kt = 0; kt < 6; kt++) {
            #pragma unroll
            for (int j = 0; j < 2; j++) {
                float e0 = acc1[kt][j][0], e1 = acc1[kt][j][1];
                float e2 = acc1[kt][j][2], e3 = acc1[kt][j][3];
                float x0 = __shfl_sync(0xffffffffu, e0, srcA);
                float x1 = __shfl_sync(0xffffffffu, e1, srcA);
                float x2 = __shfl_sync(0xffffffffu, e2, srcA);
                float x3 = __shfl_sync(0xffffffffu, e3, srcA);
                float y0 = __shfl_sync(0xffffffffu, e0, srcB);
                float y1 = __shfl_sync(0xffffffffu, e1, srcB);
                float y2 = __shfl_sync(0xffffffffu, e2, srcB);
                float y3 = __shfl_sync(0xffffffffu, e3, srcB);
                uint32_t a[4];
                a[0] = f2tf32(odd ? x1 : x0);
                a[1] = f2tf32(odd ? x3 : x2);
                a[2] = f2tf32(odd ? y1 : y0);
                a[3] = f2tf32(odd ? y3 : y2);
                int kb = kt * 8 + wn * 2 + j;
                uint4 f0 = *reinterpret_cast<const uint4*>(&smu[VF_OFF + kb*256 + lane*4]);
                uint4 f1 = *reinterpret_cast<const uint4*>(&smu[VF_OFF + kb*256 + 128 + lane*4]);
                uint32_t b0[2] = {f0.x, f0.y}, b1[2] = {f0.z, f0.w};
                uint32_t b2[2] = {f1.x, f1.y}, b3[2] = {f1.z, f1.w};
                mma_tf32(acc2[0], a, b0);
                mma_tf32(acc2[1], a, b1);
                mma_tf32(acc2[2], a, b2);
                mma_tf32(acc2[3], a, b3);
            }
        }
        // ---- write split-K partials ----
        #pragma unroll
        for (int nt = 0; nt < 4; nt++) {
            int col = nt * 8 + c * 2;
            float* base = &smf[PT_OFF + wn * (64 * PT_STR)];
            *reinterpret_cast<float2*>(&base[(m0 + r) * PT_STR + col]) =
                make_float2(acc2[nt][0], acc2[nt][1]);
            *reinterpret_cast<float2*>(&base[(m0 + 8 + r) * PT_STR + col]) =
                make_float2(acc2[nt][2], acc2[nt][3]);
        }
        __syncthreads();
        // ---- reduce partials, inv row-sum, gate -> Of (aliases Qf[.][h]) ----
        {
            int row = tid >> 3;
            int c0  = (tid & 7) * 4;
            float4 s0 = *reinterpret_cast<const float4*>(&smf[PT_OFF + 0 * (64*PT_STR) + row * PT_STR + c0]);
            float4 s1 = *reinterpret_cast<const float4*>(&smf[PT_OFF + 1 * (64*PT_STR) + row * PT_STR + c0]);
            float4 s2 = *reinterpret_cast<const float4*>(&smf[PT_OFF + 2 * (64*PT_STR) + row * PT_STR + c0]);
            float4 s3 = *reinterpret_cast<const float4*>(&smf[PT_OFF + 3 * (64*PT_STR) + row * PT_STR + c0]);
            float total = smf[RED_OFF + row] + smf[RED_OFF + 64 + row]
                        + smf[RED_OFF + 128 + row] + smf[RED_OFF + 192 + row];
            float inv = 1.0f / total;
            float4 g = *reinterpret_cast<const float4*>(&g_g[(qrow0 + row) * CZ + h * CH + c0]);
            float ox = (s0.x + s1.x + s2.x + s3.x) * inv * g.x;
            float oy = (s0.y + s1.y + s2.y + s3.y) * inv * g.y;
            float oz = (s0.z + s1.z + s2.z + s3.z) * inv * g.z;
            float ow = (s0.w + s1.w + s2.w + s3.w) * inv * g.w;
            int wmo = row >> 4, rho = (row >> 3) & 1, rqo = row & 7;
            int kco = c0 >> 3, chalfo = (c0 >> 2) & 1;
            float* od = &smf[QF_OFF + wmo*2048 + h*512 + kco*128 + rqo*16 + chalfo*2 + rho];
            od[0] = ox; od[4] = oy; od[8] = oz; od[12] = ow;
        }
        __syncthreads();
    }

    // ---- stage Wo (tf32 fragment order) over dead Kf/Vf ----
    #pragma unroll
    for (int t = 0; t < 8; t++) {
        int idx = tid + t * 512;
        int rr = idx >> 5, c4 = idx & 31;     // rr = n index, k cols c4*4..+3
        float4 v = reinterpret_cast<const float4*>(Wo + (size_t)rr * CZ)[c4];
        int nb = rr >> 3, rq = rr & 7;
        int kc2 = c4 >> 2, kcl = (c4 >> 1) & 1, b = c4 & 1;
        uint32_t* dst = &smu[KF_OFF + nb*1024 + kc2*128 + rq*16 + kcl*2 + b];
        dst[0]  = f2tf32(v.x); dst[4]  = f2tf32(v.y);
        dst[8]  = f2tf32(v.z); dst[12] = f2tf32(v.w);
    }
    __syncthreads();

    // ---- fused output projection: out = Of @ Wo^T + bo ----
    float acco[4][4] = {};
    #pragma unroll
    for (int ks2 = 0; ks2 < 8; ks2++) {
        uint4 bf[4];
        #pragma unroll
        for (int nt = 0; nt < 4; nt++)
            bf[nt] = *reinterpret_cast<const uint4*>(
                &smu[KF_OFF + (wn*4 + nt)*1024 + ks2*128 + lane*4]);
        #pragma unroll
        for (int kcl = 0; kcl < 2; kcl++) {
            int ks = ks2 * 2 + kcl;
            float4 af = *reinterpret_cast<const float4*>(
                &smf[QF_OFF + wm*2048 + (ks >> 2)*512 + (ks & 3)*128 + lane*4]);
            uint32_t ah[4], al[4];
            split4(af, ah, al);
            #pragma unroll
            for (int nt = 0; nt < 4; nt++) {
                uint32_t b[2];
                b[0] = kcl ? bf[nt].z : bf[nt].x;
                b[1] = kcl ? bf[nt].w : bf[nt].y;
                mma_tf32(acco[nt], ah, b);
                mma_tf32(acco[nt], al, b);
            }
        }
    }
    const int n0o = wn * 32;
    #pragma unroll
    for (int nt = 0; nt < 4; nt++) {
        int gc = n0o + nt * 8 + c * 2;
        float bx = bo[gc], by = bo[gc + 1];
        #pragma unroll
        for (int half = 0; half < 2; half++) {
            size_t row = qrow0 + m0 + r + half * 8;
            float2 v = make_float2(acco[nt][half * 2] + bx, acco[nt][half * 2 + 1] + by);
            *reinterpret_cast<float2*>(&out[row * CZ + gc]) = v;
        }
    }
}

// ---------------- launch ----------------
extern "C" void kernel_launch(void* const* d_in, const int* in_sizes, int n_in,
                              void* d_out, int out_size)
{
    const float* z   = (const float*)d_in[0];
    const float* lnw = (const float*)d_in[1];
    const float* lnb = (const float*)d_in[2];
    const float* Wq  = (const float*)d_in[3];
    const float* Wk  = (const float*)d_in[4];
    const float* Wv  = (const float*)d_in[5];
    // d_in[6] = Wb : bias broadcasts along the key axis -> softmax-invariant -> unused
    const float* Wg  = (const float*)d_in[7];
    const float* bg  = (const float*)d_in[8];
    const float* Wo  = (const float*)d_in[9];
    const float* bo  = (const float*)d_in[10];
    float* out = (float*)d_out;
    (void)in_sizes; (void)n_in; (void)out_size;

    cudaFuncSetAttribute(proj_mma, cudaFuncAttributeMaxDynamicSharedMemorySize, PROJ_SMEM);
    cudaFuncSetAttribute(attn_mma_kernel, cudaFuncAttributeMaxDynamicSharedMemorySize, ATTN_SMEM_B);

    proj_mma<<<dim3(NROWS / 64, 2), 512, PROJ_SMEM>>>(z, lnw, lnb, Wq, Wk, Wv, Wg, bg);
    attn_mma_kernel<<<dim3(S_DIM, 6), 512, ATTN_SMEM_B>>>(Wo, bo, out);
}

// round 9
// speedup vs baseline: 1.1150x; 1.1150x over previous
#include <cuda_runtime.h>
#include <math.h>
#include <stdint.h>

#define S_DIM  384
#define CZ     128
#define H_DIM  4
#define CH     32
#define NROWS  (S_DIM*S_DIM)   // 147456

// ---------------- scratch (device globals; allocation-free) ----------------
__device__ float g_q [(size_t)NROWS*CZ];   // q projection  (col = h*32+c)
__device__ float g_g [(size_t)NROWS*CZ];   // sigmoid gate  (col = h*32+c)
__device__ float g_k [(size_t)NROWS*CH];   // k projection  [i*384+kk][c]
__device__ float g_v [(size_t)NROWS*CH];   // v projection

// ---------------- helpers ----------------
__device__ __forceinline__ uint32_t f2tf32(float f) {
    uint32_t u; asm("cvt.rna.tf32.f32 %0, %1;" : "=r"(u) : "f"(f)); return u;
}
__device__ __forceinline__ void mma_tf32(float* d, const uint32_t* a, const uint32_t* b) {
    asm volatile(
        "mma.sync.aligned.m16n8k8.row.col.f32.tf32.tf32.f32 "
        "{%0,%1,%2,%3}, {%4,%5,%6,%7}, {%8,%9}, {%0,%1,%2,%3};\n"
        : "+f"(d[0]), "+f"(d[1]), "+f"(d[2]), "+f"(d[3])
        : "r"(a[0]), "r"(a[1]), "r"(a[2]), "r"(a[3]), "r"(b[0]), "r"(b[1]));
}
// load 4 fp32 from smem (A fragment layout) and split into hi/lo tf32
__device__ __forceinline__ void load_split(const float* smf, int i0, int i1, int i2, int i3,
                                           uint32_t* ah, uint32_t* al) {
    float a0 = smf[i0], a1 = smf[i1], a2 = smf[i2], a3 = smf[i3];
    ah[0] = f2tf32(a0); al[0] = f2tf32(a0 - __uint_as_float(ah[0]));
    ah[1] = f2tf32(a1); al[1] = f2tf32(a1 - __uint_as_float(ah[1]));
    ah[2] = f2tf32(a2); al[2] = f2tf32(a2 - __uint_as_float(ah[2]));
    ah[3] = f2tf32(a3); al[3] = f2tf32(a3 - __uint_as_float(ah[3]));
}

// ---------------- kernel 1: LayerNorm + fused projections (single-pass tf32) ----------------
// q,k,v are re-rounded to tf32 by the attention kernel anyway, and the gate goes
// through a sigmoid -- exact-A hi/lo compensation here is wasted. Single MMA pass.
#define PA_STR 132
#define PB_STR 68
#define PROJ_SMEM (64*PA_STR*4 + 160*PB_STR*4)   // 77312 B
__global__ void __launch_bounds__(512, 2) proj_mma(const float* __restrict__ z,
                                                   const float* __restrict__ lnw,
                                                   const float* __restrict__ lnb,
                                                   const float* __restrict__ Wq,
                                                   const float* __restrict__ Wk,
                                                   const float* __restrict__ Wv,
                                                   const float* __restrict__ Wg,
                                                   const float* __restrict__ bg)
{
    extern __shared__ float sm[];
    uint32_t* Asu = reinterpret_cast<uint32_t*>(sm);                 // 64 x 132 tf32 (zn)
    uint32_t* Bsu = reinterpret_cast<uint32_t*>(sm + 64 * PA_STR);   // 160 x 68 tf32

    const int tid  = threadIdx.x;
    const int wid  = tid >> 5;
    const int lane = tid & 31;
    const int r = lane >> 2, c = lane & 3;
    const int wm = wid & 3, wn = wid >> 2;
    const int m0 = wm * 16, n0 = wn * 40;
    const int rowBase = blockIdx.x * 64;
    const int cg = blockIdx.y;

    // ---- fused LayerNorm -> tf32 zn in smem (8 threads per row) ----
    {
        int row = tid >> 3;
        int sub = tid & 7;
        const float4* zr = reinterpret_cast<const float4*>(z + (size_t)(rowBase + row) * CZ) + sub * 4;
        float4 x0 = zr[0], x1 = zr[1], x2 = zr[2], x3 = zr[3];
        float s  = x0.x+x0.y+x0.z+x0.w + x1.x+x1.y+x1.z+x1.w
                 + x2.x+x2.y+x2.z+x2.w + x3.x+x3.y+x3.z+x3.w;
        float ss = x0.x*x0.x+x0.y*x0.y+x0.z*x0.z+x0.w*x0.w
                 + x1.x*x1.x+x1.y*x1.y+x1.z*x1.z+x1.w*x1.w
                 + x2.x*x2.x+x2.y*x2.y+x2.z*x2.z+x2.w*x2.w
                 + x3.x*x3.x+x3.y*x3.y+x3.z*x3.z+x3.w*x3.w;
        #pragma unroll
        for (int o = 1; o < 8; o <<= 1) {
            s  += __shfl_xor_sync(0xffffffffu, s,  o);
            ss += __shfl_xor_sync(0xffffffffu, ss, o);
        }
        float mean = s * (1.0f / CZ);
        float var  = ss * (1.0f / CZ) - mean * mean;
        float rstd = rsqrtf(var + 1e-5f);
        const float4* wv4 = reinterpret_cast<const float4*>(lnw) + sub * 4;
        const float4* bv4 = reinterpret_cast<const float4*>(lnb) + sub * 4;
        float xs[16] = {x0.x,x0.y,x0.z,x0.w, x1.x,x1.y,x1.z,x1.w,
                        x2.x,x2.y,x2.z,x2.w, x3.x,x3.y,x3.z,x3.w};
        #pragma unroll
        for (int q = 0; q < 4; q++) {
            float4 wv = wv4[q], bv = bv4[q];
            float wq[4] = {wv.x, wv.y, wv.z, wv.w};
            float bq[4] = {bv.x, bv.y, bv.z, bv.w};
            #pragma unroll
            for (int e = 0; e < 4; e++) {
                float zn = (xs[q * 4 + e] - mean) * rstd * wq[e] + bq[e];
                Asu[row * PA_STR + sub * 16 + q * 4 + e] = f2tf32(zn);
            }
        }
    }

    float acc[5][4] = {};
    #pragma unroll
    for (int kh = 0; kh < 2; kh++) {
        if (kh) __syncthreads();
        #pragma unroll
        for (int t = 0; t < 5; t++) {
            int idx = tid + t * 512;
            int rr = idx >> 4, c4 = idx & 15;
            int gc = cg * 160 + rr;
            const float* wrow;
            if (gc < 128)      wrow = Wq + (size_t)gc * CZ;
            else if (gc < 160) wrow = Wk + (size_t)(gc - 128) * CZ;
            else if (gc < 192) wrow = Wv + (size_t)(gc - 160) * CZ;
            else               wrow = Wg + (size_t)(gc - 192) * CZ;
            float4 v = reinterpret_cast<const float4*>(wrow)[kh * 16 + c4];
            Bsu[rr * PB_STR + c4 * 4 + 0] = f2tf32(v.x);
            Bsu[rr * PB_STR + c4 * 4 + 1] = f2tf32(v.y);
            Bsu[rr * PB_STR + c4 * 4 + 2] = f2tf32(v.z);
            Bsu[rr * PB_STR + c4 * 4 + 3] = f2tf32(v.w);
        }
        __syncthreads();
        #pragma unroll
        for (int ks = 0; ks < 8; ks++) {
            int k0 = ks * 8;
            int ka = kh * 64 + k0;
            uint32_t ah[4];
            ah[0] = Asu[(m0 + r) * PA_STR + ka + c];
            ah[1] = Asu[(m0 + r + 8) * PA_STR + ka + c];
            ah[2] = Asu[(m0 + r) * PA_STR + ka + c + 4];
            ah[3] = Asu[(m0 + r + 8) * PA_STR + ka + c + 4];
            #pragma unroll
            for (int nt = 0; nt < 5; nt++) {
                uint32_t b[2];
                b[0] = Bsu[(n0 + nt * 8 + r) * PB_STR + k0 + c];
                b[1] = Bsu[(n0 + nt * 8 + r) * PB_STR + k0 + c + 4];
                mma_tf32(acc[nt], ah, b);
            }
        }
    }

    // ---- epilogue with routing ----
    #pragma unroll
    for (int nt = 0; nt < 5; nt++) {
        int gc = cg * 160 + n0 + nt * 8 + c * 2;
        #pragma unroll
        for (int half = 0; half < 2; half++) {
            size_t row = (size_t)rowBase + m0 + r + half * 8;
            float2 v = make_float2(acc[nt][half * 2], acc[nt][half * 2 + 1]);
            if (gc < 128)
                *reinterpret_cast<float2*>(&g_q[row * CZ + gc]) = v;
            else if (gc < 160)
                *reinterpret_cast<float2*>(&g_k[row * CH + (gc - 128)]) = v;
            else if (gc < 192)
                *reinterpret_cast<float2*>(&g_v[row * CH + (gc - 160)]) = v;
            else {
                int cc = gc - 192;
                v.x = 1.0f / (1.0f + __expf(-(v.x + bg[cc])));
                v.y = 1.0f / (1.0f + __expf(-(v.y + bg[cc + 1])));
                *reinterpret_cast<float2*>(&g_g[row * CZ + cc]) = v;
            }
        }
    }
}

// ---------------- kernel 2: attention + fused output projection (R7 layout) ----------------
#define QSTR    132
#define KSTR    36
#define VSTR    40
#define PT_STR  36
#define OSTR    132
#define RED_OFF 0                        // 256 floats [wn][64]
#define Q_OFF   256                      // 64 x 132
#define K_OFF   (Q_OFF + 64*QSTR)        // 384 x 36  (later: Wo 128 x 132 tf32)
#define V_OFF   (K_OFF + 384*KSTR)       // 384 x 40
#define PT_OFF  (V_OFF + 384*VSTR)       // 4 x 64 x 36
#define O_OFF   (PT_OFF + 4*64*PT_STR)   // 64 x 132 fp32 (gated o)
#define ATTN_SMEM_F (O_OFF + 64*OSTR)    // 55552 floats
#define ATTN_SMEM_B (ATTN_SMEM_F * 4)    // 222208 B

__global__ void __launch_bounds__(512, 1) attn_mma_kernel(const float* __restrict__ Wo,
                                                          const float* __restrict__ bo,
                                                          float* __restrict__ out)
{
    extern __shared__ float smf[];
    uint32_t* smu = reinterpret_cast<uint32_t*>(smf);
    const int tid  = threadIdx.x;
    const int wid  = tid >> 5;
    const int lane = tid & 31;
    const int wm = wid & 3;
    const int wn = wid >> 2;
    const int r  = lane >> 2;
    const int c  = lane & 3;
    const int m0 = wm * 16;
    const int i  = blockIdx.x;
    const int jt = blockIdx.y;

    const float scale = 0.17677669529663689f;
    const size_t qrow0 = (size_t)i * S_DIM + jt * 64;
    const size_t kr0   = (size_t)i * S_DIM;

    // ---- stage Q (all heads, scaled tf32): 64 x 128 ----
    #pragma unroll
    for (int t = 0; t < 4; t++) {
        int idx = tid + t * 512;
        int rr = idx >> 5, c4 = idx & 31;
        float4 v = *reinterpret_cast<const float4*>(&g_q[(qrow0 + rr) * CZ + c4 * 4]);
        uint32_t* dst = &smu[Q_OFF + rr * QSTR + c4 * 4];
        dst[0] = f2tf32(v.x * scale); dst[1] = f2tf32(v.y * scale);
        dst[2] = f2tf32(v.z * scale); dst[3] = f2tf32(v.w * scale);
    }
    // ---- stage K, V (tf32): 384 x 32 each ----
    #pragma unroll
    for (int t = 0; t < 6; t++) {
        int idx = tid + t * 512;
        int rr = idx >> 3, c4 = idx & 7;
        float4 k4 = *reinterpret_cast<const float4*>(&g_k[(kr0 + rr) * CH + c4 * 4]);
        uint32_t* kd = &smu[K_OFF + rr * KSTR + c4 * 4];
        kd[0] = f2tf32(k4.x); kd[1] = f2tf32(k4.y);
        kd[2] = f2tf32(k4.z); kd[3] = f2tf32(k4.w);
        float4 v4 = *reinterpret_cast<const float4*>(&g_v[(kr0 + rr) * CH + c4 * 4]);
        uint32_t* vd = &smu[V_OFF + rr * VSTR + c4 * 4];
        vd[0] = f2tf32(v4.x); vd[1] = f2tf32(v4.y);
        vd[2] = f2tf32(v4.z); vd[3] = f2tf32(v4.w);
    }
    __syncthreads();

    const int srcA = (lane & ~3) | (c >> 1);
    const int srcB = srcA + 2;
    const bool odd = (c & 1) != 0;

    for (int h = 0; h < H_DIM; h++) {
        uint32_t afrag[4][4];
        #pragma unroll
        for (int kc = 0; kc < 4; kc++) {
            int base = Q_OFF + h * CH + kc * 8 + c;
            afrag[kc][0] = smu[base + (m0 + r) * QSTR];
            afrag[kc][1] = smu[base + (m0 + r + 8) * QSTR];
            afrag[kc][2] = smu[base + (m0 + r) * QSTR + 4];
            afrag[kc][3] = smu[base + (m0 + r + 8) * QSTR + 4];
        }
        float acc1[6][2][4] = {};
        #pragma unroll
        for (int kt = 0; kt < 6; kt++) {
            #pragma unroll
            for (int kc = 0; kc < 4; kc++) {
                #pragma unroll
                for (int j = 0; j < 2; j++) {
                    int n = kt * 64 + wn * 16 + j * 8;
                    uint32_t b[2];
                    b[0] = smu[K_OFF + (n + r) * KSTR + kc * 8 + c];
                    b[1] = smu[K_OFF + (n + r) * KSTR + kc * 8 + c + 4];
                    mma_tf32(acc1[kt][j], afrag[kc], b);
                }
            }
        }
        float rs0 = 0.0f, rs1 = 0.0f;
        #pragma unroll
        for (int kt = 0; kt < 6; kt++) {
            #pragma unroll
            for (int j = 0; j < 2; j++) {
                acc1[kt][j][0] = __expf(acc1[kt][j][0]);
                acc1[kt][j][1] = __expf(acc1[kt][j][1]);
                acc1[kt][j][2] = __expf(acc1[kt][j][2]);
                acc1[kt][j][3] = __expf(acc1[kt][j][3]);
                rs0 += acc1[kt][j][0] + acc1[kt][j][1];
                rs1 += acc1[kt][j][2] + acc1[kt][j][3];
            }
        }
        rs0 += __shfl_xor_sync(0xffffffffu, rs0, 1);
        rs0 += __shfl_xor_sync(0xffffffffu, rs0, 2);
        rs1 += __shfl_xor_sync(0xffffffffu, rs1, 1);
        rs1 += __shfl_xor_sync(0xffffffffu, rs1, 2);
        if (c == 0) {
            smf[RED_OFF + wn * 64 + m0 + r] = rs0;
            smf[RED_OFF + wn * 64 + m0 + 8 + r] = rs1;
        }
        // ---- GEMM2 split-K with register P (C->A via quad shuffles) ----
        float acc2[4][4] = {};
        #pragma unroll
        for (int kt = 0; kt < 6; kt++) {
            #pragma unroll
            for (int j = 0; j < 2; j++) {
                float e0 = acc1[kt][j][0], e1 = acc1[kt][j][1];
                float e2 = acc1[kt][j][2], e3 = acc1[kt][j][3];
                float x0 = __shfl_sync(0xffffffffu, e0, srcA);
                float x1 = __shfl_sync(0xffffffffu, e1, srcA);
                float x2 = __shfl_sync(0xffffffffu, e2, srcA);
                float x3 = __shfl_sync(0xffffffffu, e3, srcA);
                float y0 = __shfl_sync(0xffffffffu, e0, srcB);
                float y1 = __shfl_sync(0xffffffffu, e1, srcB);
                float y2 = __shfl_sync(0xffffffffu, e2, srcB);
                float y3 = __shfl_sync(0xffffffffu, e3, srcB);
                uint32_t a[4];
                a[0] = f2tf32(odd ? x1 : x0);
                a[1] = f2tf32(odd ? x3 : x2);
                a[2] = f2tf32(odd ? y1 : y0);
                a[3] = f2tf32(odd ? y3 : y2);
                int k0 = kt * 64 + wn * 16 + j * 8;
                #pragma unroll
                for (int nt = 0; nt < 4; nt++) {
                    uint32_t b[2];
                    b[0] = smu[V_OFF + (k0 + c) * VSTR + nt * 8 + r];
                    b[1] = smu[V_OFF + (k0 + c + 4) * VSTR + nt * 8 + r];
                    mma_tf32(acc2[nt], a, b);
                }
            }
        }
        #pragma unroll
        for (int nt = 0; nt < 4; nt++) {
            int col = nt * 8 + c * 2;
            float* base = &smf[PT_OFF + wn * (64 * PT_STR)];
            *reinterpret_cast<float2*>(&base[(m0 + r) * PT_STR + col]) =
                make_float2(acc2[nt][0], acc2[nt][1]);
            *reinterpret_cast<float2*>(&base[(m0 + 8 + r) * PT_STR + col]) =
                make_float2(acc2[nt][2], acc2[nt][3]);
        }
        __syncthreads();
        // ---- reduce partials, inv row-sum, gate -> O smem ----
        {
            int row = tid >> 3;
            int c0  = (tid & 7) * 4;
            float4 s0 = *reinterpret_cast<const float4*>(&smf[PT_OFF + 0 * (64*PT_STR) + row * PT_STR + c0]);
            float4 s1 = *reinterpret_cast<const float4*>(&smf[PT_OFF + 1 * (64*PT_STR) + row * PT_STR + c0]);
            float4 s2 = *reinterpret_cast<const float4*>(&smf[PT_OFF + 2 * (64*PT_STR) + row * PT_STR + c0]);
            float4 s3 = *reinterpret_cast<const float4*>(&smf[PT_OFF + 3 * (64*PT_STR) + row * PT_STR + c0]);
            float total = smf[RED_OFF + row] + smf[RED_OFF + 64 + row]
                        + smf[RED_OFF + 128 + row] + smf[RED_OFF + 192 + row];
            float inv = 1.0f / total;
            float4 g = *reinterpret_cast<const float4*>(&g_g[(qrow0 + row) * CZ + h * CH + c0]);
            float4 o;
            o.x = (s0.x + s1.x + s2.x + s3.x) * inv * g.x;
            o.y = (s0.y + s1.y + s2.y + s3.y) * inv * g.y;
            o.z = (s0.z + s1.z + s2.z + s3.z) * inv * g.z;
            o.w = (s0.w + s1.w + s2.w + s3.w) * inv * g.w;
            *reinterpret_cast<float4*>(&smf[O_OFF + row * OSTR + h * CH + c0]) = o;
        }
        __syncthreads();
    }

    // ---- fused output projection: out = O @ Wo^T + bo (hi/lo exact A) ----
    #pragma unroll
    for (int t = 0; t < 8; t++) {
        int idx = tid + t * 512;
        int rr = idx >> 5, c4 = idx & 31;
        float4 v = reinterpret_cast<const float4*>(Wo + (size_t)rr * CZ)[c4];
        uint32_t* dst = &smu[K_OFF + rr * QSTR + c4 * 4];
        dst[0] = f2tf32(v.x); dst[1] = f2tf32(v.y);
        dst[2] = f2tf32(v.z); dst[3] = f2tf32(v.w);
    }
    __syncthreads();

    float acco[4][4] = {};
    const int n0o = wn * 32;
    #pragma unroll
    for (int ks = 0; ks < 16; ks++) {
        int k0 = ks * 8;
        uint32_t ah[4], al[4];
        load_split(smf,
            O_OFF + (m0 + r) * OSTR + k0 + c,     O_OFF + (m0 + r + 8) * OSTR + k0 + c,
            O_OFF + (m0 + r) * OSTR + k0 + c + 4, O_OFF + (m0 + r + 8) * OSTR + k0 + c + 4,
            ah, al);
        #pragma unroll
        for (int nt = 0; nt < 4; nt++) {
            uint32_t b[2];
            b[0] = smu[K_OFF + (n0o + nt * 8 + r) * QSTR + k0 + c];
            b[1] = smu[K_OFF + (n0o + nt * 8 + r) * QSTR + k0 + c + 4];
            mma_tf32(acco[nt], ah, b);
            mma_tf32(acco[nt], al, b);
        }
    }
    #pragma unroll
    for (int nt = 0; nt < 4; nt++) {
        int gc = n0o + nt * 8 + c * 2;
        float bx = bo[gc], by = bo[gc + 1];
        #pragma unroll
        for (int half = 0; half < 2; half++) {
            size_t row = qrow0 + m0 + r + half * 8;
            float2 v = make_float2(acco[nt][half * 2] + bx, acco[nt][half * 2 + 1] + by);
            *reinterpret_cast<float2*>(&out[row * CZ + gc]) = v;
        }
    }
}

// ---------------- launch ----------------
extern "C" void kernel_launch(void* const* d_in, const int* in_sizes, int n_in,
                              void* d_out, int out_size)
{
    const float* z   = (const float*)d_in[0];
    const float* lnw = (const float*)d_in[1];
    const float* lnb = (const float*)d_in[2];
    const float* Wq  = (const float*)d_in[3];
    const float* Wk  = (const float*)d_in[4];
    const float* Wv  = (const float*)d_in[5];
    // d_in[6] = Wb : bias broadcasts along the key axis -> softmax-invariant -> unused
    const float* Wg  = (const float*)d_in[7];
    const float* bg  = (const float*)d_in[8];
    const float* Wo  = (const float*)d_in[9];
    const float* bo  = (const float*)d_in[10];
    float* out = (float*)d_out;
    (void)in_sizes; (void)n_in; (void)out_size;

    cudaFuncSetAttribute(proj_mma, cudaFuncAttributeMaxDynamicSharedMemorySize, PROJ_SMEM);
    cudaFuncSetAttribute(attn_mma_kernel, cudaFuncAttributeMaxDynamicSharedMemorySize, ATTN_SMEM_B);

    proj_mma<<<dim3(NROWS / 64, 2), 512, PROJ_SMEM>>>(z, lnw, lnb, Wq, Wk, Wv, Wg, bg);
    attn_mma_kernel<<<dim3(S_DIM, 6), 512, ATTN_SMEM_B>>>(Wo, bo, out);
}